// round 7
// baseline (speedup 1.0000x reference)
#include <cuda_runtime.h>
#include <cuda_fp16.h>
#include <math.h>
#include <stdint.h>

#define NQ   512
#define NC   16
#define CS   64
#define HID  128
#define NB   2048
#define ROUNDS 4
#define GRID   148
#define THREADS 512

#define WST  272          // padded fp16 row stride in bytes (128 halfs + 8 pad)

// ---- smem offsets ----
#define OFF_TAB  0                          // 512*256   = 131072
#define OFF_W    131072                     // 128*272   = 34816
#define OFF_M    165888                     // 64*272    = 17408
#define OFF_BUF  183296                     // 4*16*64*2 = 8192
#define OFF_CE   191488                     // 4*16*32*8 = 16384
#define OFF_AN2  207872                     // 256*8     = 2048
#define OFF_BIAS 209920                     // 512
#define OFF_CNT  210432                     // 64*4      = 256
#define SMEM_REQ 210944

__device__ float g_anorm[NC * NC];
__device__ __align__(16) __half g_embh[(NQ + 1) * HID];
__device__ __align__(16) __half g_Wh[HID * HID];   // W[o][h], fp16

typedef unsigned long long u64;

static __device__ __forceinline__ uint32_t smem_u32(const void* p) {
    uint32_t a;
    asm("{ .reg .u64 t; cvta.to.shared.u64 t, %1; cvt.u32.u64 %0, t; }" : "=r"(a) : "l"(p));
    return a;
}
static __device__ __forceinline__ u64 pack2(float lo, float hi) {
    u64 r; asm("mov.b64 %0, {%1, %2};" : "=l"(r) : "f"(lo), "f"(hi)); return r;
}
static __device__ __forceinline__ void ffma2(u64 &d, u64 a, u64 b) {
    asm("fma.rn.f32x2 %0, %1, %2, %0;" : "+l"(d) : "l"(a), "l"(b));
}
static __device__ __forceinline__ float2 unpack2(u64 v) {
    float x, y; asm("mov.b64 {%0, %1}, %2;" : "=f"(x), "=f"(y) : "l"(v));
    return make_float2(x, y);
}
static __device__ __forceinline__ void ldsm_x4(uint32_t* r, uint32_t addr) {
    asm volatile("ldmatrix.sync.aligned.m8n8.x4.shared.b16 {%0,%1,%2,%3}, [%4];"
        : "=r"(r[0]), "=r"(r[1]), "=r"(r[2]), "=r"(r[3]) : "r"(addr));
}
static __device__ __forceinline__ void mma16816(float* d, const uint32_t* a, const uint32_t* b) {
    asm volatile("mma.sync.aligned.m16n8k16.row.col.f32.f16.f16.f32 "
        "{%0,%1,%2,%3}, {%4,%5,%6,%7}, {%8,%9}, {%0,%1,%2,%3};"
        : "+f"(d[0]), "+f"(d[1]), "+f"(d[2]), "+f"(d[3])
        : "r"(a[0]), "r"(a[1]), "r"(a[2]), "r"(a[3]), "r"(b[0]), "r"(b[1]));
}

// ---------------- prep: anorm, fp16 table, fp16 W ----------------
__global__ void prep_kernel(const float* __restrict__ adj,
                            const float* __restrict__ W,
                            const float* __restrict__ qemb) {
    int t = threadIdx.x, b = blockIdx.x;
    if (b < 64) {
        int idx = b * 256 + t;                 // 16384 W entries
        g_Wh[idx] = __float2half(W[idx]);
    } else if (b == 64) {
        int i = t >> 4, j = t & 15;
        float di = 0.f, dj = 0.f;
#pragma unroll
        for (int r = 0; r < NC; r++) { di += adj[r * NC + i]; dj += adj[r * NC + j]; }
        di = di > 0.f ? rsqrtf(di) : 0.f;
        dj = dj > 0.f ? rsqrtf(dj) : 0.f;
        g_anorm[t] = adj[t] * di * dj;
    } else {
        int idx = (b - 65) * 256 + t;
        if (idx < (NQ + 1) * HID) g_embh[idx] = __float2half(qemb[idx]);
    }
}

// ---------------- fused: smem table -> ballot-bucket -> pool -> mix -> mma.sync GEMM ----------------
__global__ void __launch_bounds__(THREADS, 1)
enc_kernel(const int*   __restrict__ la,
           const float* __restrict__ bias,
           float*       __restrict__ out)
{
    extern __shared__ __align__(16) char smem[];
    const uint32_t sb = smem_u32(smem);

    const int tid  = threadIdx.x;
    const int lane = tid & 31;
    const int w    = tid >> 5;
    const int blk  = blockIdx.x;

    // 2048 = 124*14 + 24*13
    const int b0     = blk * 13 + (blk < 124 ? blk : 124);
    const int nbatch = 13 + (blk < 124 ? 1 : 0);

    unsigned short* s_buf  = (unsigned short*)(smem + OFF_BUF);
    int*            s_cnt  = (int*)(smem + OFF_CNT);
    u64*            s_an2  = (u64*)(smem + OFF_AN2);
    float*          s_bias = (float*)(smem + OFF_BIAS);

    // ---- phase 0: constants + table + W into smem ----
    if (tid < 256) { float a = g_anorm[tid]; s_an2[tid] = pack2(a, a); }
    else if (tid < 384) s_bias[tid - 256] = bias[tid - 256];
    {
        const uint4* src = (const uint4*)g_embh;
        uint4* dst = (uint4*)(smem + OFF_TAB);
#pragma unroll
        for (int i = 0; i < 16; i++) dst[i * THREADS + tid] = src[i * THREADS + tid];
    }
    {
        const uint4* src = (const uint4*)g_Wh;
#pragma unroll
        for (int k = 0; k < 4; k++) {
            int idx = k * THREADS + tid;          // 2048 uint4
            int o = idx >> 4, seg = idx & 15;
            *(uint4*)(smem + OFF_W + o * WST + seg * 16) = src[idx];
        }
    }
    __syncthreads();

    for (int R = 0; R < ROUNDS; R++) {
        const int nb = min(4, nbatch - R * 4);   // active batches this round (>=1)

        // ---- bucket: ballot-based, atomic-free, exact qubit order. warps 0..nb-1 ----
        if (w < nb) {
            const int batch = b0 + R * 4 + w;
            const int* lr = la + (size_t)batch * NQ;
            int av[16];
#pragma unroll
            for (int it = 0; it < 16; it++) av[it] = lr[it * 32 + lane];

            const unsigned lt = (1u << lane) - 1u;
            int base[NC];
#pragma unroll
            for (int c = 0; c < NC; c++) base[c] = 0;

#pragma unroll
            for (int it = 0; it < 16; it++) {
                const int a = av[it];
                const int qb = it * 32;
#pragma unroll
                for (int c = 0; c < NC; c++) {
                    unsigned m = __ballot_sync(0xFFFFFFFFu, a == c);
                    if (a == c) {
                        int pos = base[c] + __popc(m & lt);
                        if (pos < CS)
                            s_buf[(w * NC + c) * CS + pos] = (unsigned short)(qb + lane);
                    }
                    base[c] += __popc(m);
                }
            }
#pragma unroll
            for (int c = 0; c < NC; c++)
                if (lane == c) s_cnt[w * NC + c] = base[c];
        } else if (w == 4 || w == 5) {
            // zero counts of inactive batch slots (partial last round)
            int idx = (w - 4) * 32 + lane;
            if (idx < (4 - nb) * NC) s_cnt[nb * NC + idx] = 0;
        }
        __syncthreads();

        // ---- pool from smem table: warp -> (batch w>>2, cores (w&3)*4..+3) ----
        {
            const int bb = w >> 2;
            const int c0 = (w & 3) * 4;
            uint2* ce = (uint2*)(smem + OFF_CE);
#pragma unroll
            for (int cc = 0; cc < 4; cc++) {
                int c = c0 + cc;
                int cnt = s_cnt[bb * NC + c];
                int n = cnt < CS ? cnt : CS;
                __half2 a0 = __half2half2(__ushort_as_half(
                                 (unsigned short)(cnt >= CS ? 0xFC00 : 0)));
                __half2 a1 = a0;
                const unsigned short* bq = &s_buf[(bb * NC + c) * CS];
                int i = 0;
                for (; i + 4 <= n; i += 4) {
                    u64 qq = *(const u64*)(bq + i);
                    uint32_t q0 = (uint32_t)(qq) & 0xFFFFu;
                    uint32_t q1 = (uint32_t)(qq >> 16) & 0xFFFFu;
                    uint32_t q2 = (uint32_t)(qq >> 32) & 0xFFFFu;
                    uint32_t q3 = (uint32_t)(qq >> 48) & 0xFFFFu;
                    uint2 r0 = *(const uint2*)(smem + OFF_TAB + q0 * 256u + lane * 8u);
                    uint2 r1 = *(const uint2*)(smem + OFF_TAB + q1 * 256u + lane * 8u);
                    uint2 r2 = *(const uint2*)(smem + OFF_TAB + q2 * 256u + lane * 8u);
                    uint2 r3 = *(const uint2*)(smem + OFF_TAB + q3 * 256u + lane * 8u);
                    a0 = __hmax2(a0, *(__half2*)&r0.x); a1 = __hmax2(a1, *(__half2*)&r0.y);
                    a0 = __hmax2(a0, *(__half2*)&r1.x); a1 = __hmax2(a1, *(__half2*)&r1.y);
                    a0 = __hmax2(a0, *(__half2*)&r2.x); a1 = __hmax2(a1, *(__half2*)&r2.y);
                    a0 = __hmax2(a0, *(__half2*)&r3.x); a1 = __hmax2(a1, *(__half2*)&r3.y);
                }
                for (; i < n; i++) {
                    uint32_t q = bq[i];
                    uint2 r0 = *(const uint2*)(smem + OFF_TAB + q * 256u + lane * 8u);
                    a0 = __hmax2(a0, *(__half2*)&r0.x); a1 = __hmax2(a1, *(__half2*)&r0.y);
                }
                uint2 st;
                st.x = *(uint32_t*)&a0; st.y = *(uint32_t*)&a1;
                ce[(bb * NC + c) * 32 + lane] = st;
            }
        }
        __syncthreads();

        // ---- mix: warp -> (batch w>>2, i-group w&3); lane owns 4 h-cols ----
        {
            const int bb = w >> 2, ig = w & 3;
            const uint2* cep = (const uint2*)(smem + OFF_CE) + (bb * NC) * 32 + lane;
            u64 mlo[4], mhi[4];
#pragma unroll
            for (int ii = 0; ii < 4; ii++) { mlo[ii] = 0ull; mhi[ii] = 0ull; }
#pragma unroll
            for (int j = 0; j < NC; j++) {
                uint2 cu = cep[j * 32];
                float2 flo = __half22float2(*(__half2*)&cu.x);
                float2 fhi = __half22float2(*(__half2*)&cu.y);
                u64 vlo = pack2(flo.x, flo.y);
                u64 vhi = pack2(fhi.x, fhi.y);
#pragma unroll
                for (int ii = 0; ii < 4; ii++) {
                    u64 ap = s_an2[(ig * 4 + ii) * NC + j];
                    ffma2(mlo[ii], vlo, ap);
                    ffma2(mhi[ii], vhi, ap);
                }
            }
#pragma unroll
            for (int ii = 0; ii < 4; ii++) {
                int r = bb * NC + ig * 4 + ii;     // 0..63
                float2 l = unpack2(mlo[ii]);
                float2 h = unpack2(mhi[ii]);
                __half2 h0 = __floats2half2_rn(l.x, l.y);
                __half2 h1 = __floats2half2_rn(h.x, h.y);
                uint2 st; st.x = *(uint32_t*)&h0; st.y = *(uint32_t*)&h1;
                *(uint2*)(smem + OFF_M + r * WST + lane * 8) = st;
            }
        }
        __syncthreads();

        // ---- GEMM: D[64,128] = M[64,128] x W[128,128]^T via mma.sync ----
        {
            const int rt = w & 3;        // row tile = batch in round
            const int ct = w >> 2;       // col tile (32 cols)
            float d[4][4];
#pragma unroll
            for (int nt = 0; nt < 4; nt++)
#pragma unroll
                for (int k = 0; k < 4; k++) d[nt][k] = 0.f;

            const uint32_t aBase = sb + OFF_M
                + (uint32_t)(rt * 16 + (lane & 15)) * WST + (uint32_t)((lane >> 4) * 16);
            const uint32_t bBase0 = sb + OFF_W
                + (uint32_t)(ct * 32 + (lane & 7) + ((lane >> 4) * 8)) * WST
                + (uint32_t)(((lane >> 3) & 1) * 16);
            const uint32_t bBase1 = bBase0 + 16 * WST;

#pragma unroll
            for (int s = 0; s < 8; s++) {
                uint32_t a[4], b0r[4], b1r[4];
                ldsm_x4(a,   aBase  + s * 32);
                ldsm_x4(b0r, bBase0 + s * 32);
                ldsm_x4(b1r, bBase1 + s * 32);
                mma16816(d[0], a, b0r + 0);
                mma16816(d[1], a, b0r + 2);
                mma16816(d[2], a, b1r + 0);
                mma16816(d[3], a, b1r + 2);
            }

            // ---- epilogue: bias + direct stores (guarded for partial rounds) ----
            if (rt < nb) {
                const int g = lane >> 2, t = lane & 3;
                float* ob = out + (size_t)(b0 + R * 4 + rt) * (NC * HID);
                float* o0 = ob + g * HID;
                float* o1 = ob + (g + 8) * HID;
#pragma unroll
                for (int nt = 0; nt < 4; nt++) {
                    int col = ct * 32 + nt * 8 + 2 * t;
                    float bv0 = s_bias[col], bv1 = s_bias[col + 1];
                    *(float2*)(o0 + col) = make_float2(d[nt][0] + bv0, d[nt][1] + bv1);
                    *(float2*)(o1 + col) = make_float2(d[nt][2] + bv0, d[nt][3] + bv1);
                }
            }
        }
        __syncthreads();
    }
}

extern "C" void kernel_launch(void* const* d_in, const int* in_sizes, int n_in,
                              void* d_out, int out_size) {
    const int*   la   = (const int*)  d_in[0];   // (2048, 512) int32
    const float* adj  = (const float*)d_in[1];   // (16, 16) f32
    const float* qemb = (const float*)d_in[2];   // (513, 128) f32
    const float* W    = (const float*)d_in[3];   // (128, 128) f32
    const float* bias = (const float*)d_in[4];   // (128,) f32
    float* out = (float*)d_out;                  // (2048, 16, 128) f32

    cudaFuncSetAttribute(enc_kernel, cudaFuncAttributeMaxDynamicSharedMemorySize, SMEM_REQ);
    prep_kernel<<<322, 256>>>(adj, W, qemb);
    enc_kernel<<<GRID, THREADS, SMEM_REQ>>>(la, bias, out);
}

// round 8
// speedup vs baseline: 2.5399x; 2.5399x over previous
#include <cuda_runtime.h>
#include <cuda_fp16.h>
#include <math.h>
#include <stdint.h>

#define NQ   512
#define NC   16
#define CS   64
#define HID  128
#define NB   2048
#define ROUNDS 4
#define GRID   148
#define THREADS 512

#define WST  272          // padded fp16 row stride in bytes (128 halfs + 8 pad)

// ---- smem offsets ----
#define OFF_TAB  0                          // 512*256   = 131072
#define OFF_W    131072                     // 128*272   = 34816
#define OFF_M    165888                     // 64*272    = 17408
#define OFF_BUF  183296                     // 4*16*64*2 = 8192
#define OFF_CE   191488                     // 4*16*32*8 = 16384
#define OFF_AN2  207872                     // 256*8     = 2048
#define OFF_BIAS 209920                     // 512
#define OFF_CNT  210432                     // 64*4      = 256
#define SMEM_REQ 210944

__device__ float g_anorm[NC * NC];
__device__ __align__(16) __half g_embh[(NQ + 1) * HID];
__device__ __align__(16) __half g_Wh[HID * HID];   // W[o][h], fp16

typedef unsigned long long u64;

static __device__ __forceinline__ uint32_t smem_u32(const void* p) {
    uint32_t a;
    asm("{ .reg .u64 t; cvta.to.shared.u64 t, %1; cvt.u32.u64 %0, t; }" : "=r"(a) : "l"(p));
    return a;
}
static __device__ __forceinline__ u64 pack2(float lo, float hi) {
    u64 r; asm("mov.b64 %0, {%1, %2};" : "=l"(r) : "f"(lo), "f"(hi)); return r;
}
static __device__ __forceinline__ void ffma2(u64 &d, u64 a, u64 b) {
    asm("fma.rn.f32x2 %0, %1, %2, %0;" : "+l"(d) : "l"(a), "l"(b));
}
static __device__ __forceinline__ float2 unpack2(u64 v) {
    float x, y; asm("mov.b64 {%0, %1}, %2;" : "=f"(x), "=f"(y) : "l"(v));
    return make_float2(x, y);
}
static __device__ __forceinline__ void ldsm_x4(uint32_t* r, uint32_t addr) {
    asm volatile("ldmatrix.sync.aligned.m8n8.x4.shared.b16 {%0,%1,%2,%3}, [%4];"
        : "=r"(r[0]), "=r"(r[1]), "=r"(r[2]), "=r"(r[3]) : "r"(addr));
}
static __device__ __forceinline__ void mma16816(float* d, const uint32_t* a, const uint32_t* b) {
    asm volatile("mma.sync.aligned.m16n8k16.row.col.f32.f16.f16.f32 "
        "{%0,%1,%2,%3}, {%4,%5,%6,%7}, {%8,%9}, {%0,%1,%2,%3};"
        : "+f"(d[0]), "+f"(d[1]), "+f"(d[2]), "+f"(d[3])
        : "r"(a[0]), "r"(a[1]), "r"(a[2]), "r"(a[3]), "r"(b[0]), "r"(b[1]));
}

// ---------------- prep: anorm, fp16 table, fp16 W ----------------
__global__ void prep_kernel(const float* __restrict__ adj,
                            const float* __restrict__ W,
                            const float* __restrict__ qemb) {
    int t = threadIdx.x, b = blockIdx.x;
    if (b < 64) {
        int idx = b * 256 + t;                 // 16384 W entries
        g_Wh[idx] = __float2half(W[idx]);
    } else if (b == 64) {
        int i = t >> 4, j = t & 15;
        float di = 0.f, dj = 0.f;
#pragma unroll
        for (int r = 0; r < NC; r++) { di += adj[r * NC + i]; dj += adj[r * NC + j]; }
        di = di > 0.f ? rsqrtf(di) : 0.f;
        dj = dj > 0.f ? rsqrtf(dj) : 0.f;
        g_anorm[t] = adj[t] * di * dj;
    } else {
        int idx = (b - 65) * 256 + t;
        if (idx < (NQ + 1) * HID) g_embh[idx] = __float2half(qemb[idx]);
    }
}

// ---------------- fused: smem table -> atomic bucket -> pool -> mix -> mma.sync GEMM ----------------
__global__ void __launch_bounds__(THREADS, 1)
enc_kernel(const int*   __restrict__ la,
           const float* __restrict__ bias,
           float*       __restrict__ out)
{
    extern __shared__ __align__(16) char smem[];
    const uint32_t sb = smem_u32(smem);

    const int tid  = threadIdx.x;
    const int lane = tid & 31;
    const int w    = tid >> 5;
    const int blk  = blockIdx.x;

    // 2048 = 124*14 + 24*13
    const int b0     = blk * 13 + (blk < 124 ? blk : 124);
    const int nbatch = 13 + (blk < 124 ? 1 : 0);

    unsigned short* s_buf  = (unsigned short*)(smem + OFF_BUF);
    int*            s_cnt  = (int*)(smem + OFF_CNT);
    u64*            s_an2  = (u64*)(smem + OFF_AN2);
    float*          s_bias = (float*)(smem + OFF_BIAS);

    // ---- phase 0: constants + table + W into smem ----
    if (tid < 256) { float a = g_anorm[tid]; s_an2[tid] = pack2(a, a); }
    else if (tid < 384) s_bias[tid - 256] = bias[tid - 256];
    {
        const uint4* src = (const uint4*)g_embh;
        uint4* dst = (uint4*)(smem + OFF_TAB);
#pragma unroll
        for (int i = 0; i < 16; i++) dst[i * THREADS + tid] = src[i * THREADS + tid];
    }
    {
        const uint4* src = (const uint4*)g_Wh;
#pragma unroll
        for (int k = 0; k < 4; k++) {
            int idx = k * THREADS + tid;          // 2048 uint4
            int o = idx >> 4, seg = idx & 15;
            *(uint4*)(smem + OFF_W + o * WST + seg * 16) = src[idx];
        }
    }
    __syncthreads();

    for (int R = 0; R < ROUNDS; R++) {
        const int nb = min(4, nbatch - R * 4);   // active batches this round (>=1)

        // ---- bucket: warps 0..3, fully warp-local (zero + atomics + fallback) ----
        if (w < 4) {
            const int cb = w * NC;
            if (lane < NC) s_cnt[cb + lane] = 0;
            __syncwarp();
            if (w < nb) {
                const int batch = b0 + R * 4 + w;
                const int4* ap = (const int4*)(la + (size_t)batch * NQ);
                bool ovf = false;
#pragma unroll
                for (int it = 0; it < 4; it++) {
                    int4 v = ap[it * 32 + lane];
                    int q0 = (it * 32 + lane) * 4;
                    int p;
                    p = atomicAdd(&s_cnt[cb + v.x], 1); if (p < CS) s_buf[(cb + v.x) * CS + p] = (unsigned short)(q0 + 0); else ovf = true;
                    p = atomicAdd(&s_cnt[cb + v.y], 1); if (p < CS) s_buf[(cb + v.y) * CS + p] = (unsigned short)(q0 + 1); else ovf = true;
                    p = atomicAdd(&s_cnt[cb + v.z], 1); if (p < CS) s_buf[(cb + v.z) * CS + p] = (unsigned short)(q0 + 2); else ovf = true;
                    p = atomicAdd(&s_cnt[cb + v.w], 1); if (p < CS) s_buf[(cb + v.w) * CS + p] = (unsigned short)(q0 + 3); else ovf = true;
                }
                // rare overflow: qubit-order-correct serial redo (warp-local)
                if (__any_sync(0xFFFFFFFFu, ovf)) {
                    if (lane == 0) {
                        int cnt[NC];
#pragma unroll
                        for (int c = 0; c < NC; c++) cnt[c] = 0;
                        for (int q = 0; q < NQ; q++) {
                            int c = la[(size_t)batch * NQ + q];
                            int p = cnt[c];
                            if (p < CS) s_buf[(cb + c) * CS + p] = (unsigned short)q;
                            cnt[c] = p + 1;
                        }
#pragma unroll
                        for (int c = 0; c < NC; c++) s_cnt[cb + c] = cnt[c];
                    }
                    __syncwarp();
                }
            }
        }
        __syncthreads();

        // ---- pool from smem table: warp -> (batch w>>2, cores (w&3)*4..+3) ----
        {
            const int bb = w >> 2;
            const int c0 = (w & 3) * 4;
            uint2* ce = (uint2*)(smem + OFF_CE);
#pragma unroll
            for (int cc = 0; cc < 4; cc++) {
                int c = c0 + cc;
                int cnt = s_cnt[bb * NC + c];
                int n = cnt < CS ? cnt : CS;
                __half2 a0 = __half2half2(__ushort_as_half(
                                 (unsigned short)(cnt >= CS ? 0xFC00 : 0)));
                __half2 a1 = a0;
                const unsigned short* bq = &s_buf[(bb * NC + c) * CS];
                int i = 0;
                for (; i + 4 <= n; i += 4) {
                    u64 qq = *(const u64*)(bq + i);
                    uint32_t q0 = (uint32_t)(qq) & 0xFFFFu;
                    uint32_t q1 = (uint32_t)(qq >> 16) & 0xFFFFu;
                    uint32_t q2 = (uint32_t)(qq >> 32) & 0xFFFFu;
                    uint32_t q3 = (uint32_t)(qq >> 48) & 0xFFFFu;
                    uint2 r0 = *(const uint2*)(smem + OFF_TAB + q0 * 256u + lane * 8u);
                    uint2 r1 = *(const uint2*)(smem + OFF_TAB + q1 * 256u + lane * 8u);
                    uint2 r2 = *(const uint2*)(smem + OFF_TAB + q2 * 256u + lane * 8u);
                    uint2 r3 = *(const uint2*)(smem + OFF_TAB + q3 * 256u + lane * 8u);
                    a0 = __hmax2(a0, *(__half2*)&r0.x); a1 = __hmax2(a1, *(__half2*)&r0.y);
                    a0 = __hmax2(a0, *(__half2*)&r1.x); a1 = __hmax2(a1, *(__half2*)&r1.y);
                    a0 = __hmax2(a0, *(__half2*)&r2.x); a1 = __hmax2(a1, *(__half2*)&r2.y);
                    a0 = __hmax2(a0, *(__half2*)&r3.x); a1 = __hmax2(a1, *(__half2*)&r3.y);
                }
                for (; i < n; i++) {
                    uint32_t q = bq[i];
                    uint2 r0 = *(const uint2*)(smem + OFF_TAB + q * 256u + lane * 8u);
                    a0 = __hmax2(a0, *(__half2*)&r0.x); a1 = __hmax2(a1, *(__half2*)&r0.y);
                }
                uint2 st;
                st.x = *(uint32_t*)&a0; st.y = *(uint32_t*)&a1;
                ce[(bb * NC + c) * 32 + lane] = st;
            }
        }
        __syncthreads();

        // ---- mix: warp -> (batch w>>2, i-group w&3); lane owns 4 h-cols ----
        {
            const int bb = w >> 2, ig = w & 3;
            const uint2* cep = (const uint2*)(smem + OFF_CE) + (bb * NC) * 32 + lane;
            u64 mlo[4], mhi[4];
#pragma unroll
            for (int ii = 0; ii < 4; ii++) { mlo[ii] = 0ull; mhi[ii] = 0ull; }
#pragma unroll
            for (int j = 0; j < NC; j++) {
                uint2 cu = cep[j * 32];
                float2 flo = __half22float2(*(__half2*)&cu.x);
                float2 fhi = __half22float2(*(__half2*)&cu.y);
                u64 vlo = pack2(flo.x, flo.y);
                u64 vhi = pack2(fhi.x, fhi.y);
#pragma unroll
                for (int ii = 0; ii < 4; ii++) {
                    u64 ap = s_an2[(ig * 4 + ii) * NC + j];
                    ffma2(mlo[ii], vlo, ap);
                    ffma2(mhi[ii], vhi, ap);
                }
            }
#pragma unroll
            for (int ii = 0; ii < 4; ii++) {
                int r = bb * NC + ig * 4 + ii;     // 0..63
                float2 l = unpack2(mlo[ii]);
                float2 h = unpack2(mhi[ii]);
                __half2 h0 = __floats2half2_rn(l.x, l.y);
                __half2 h1 = __floats2half2_rn(h.x, h.y);
                uint2 st; st.x = *(uint32_t*)&h0; st.y = *(uint32_t*)&h1;
                *(uint2*)(smem + OFF_M + r * WST + lane * 8) = st;
            }
        }
        __syncthreads();

        // ---- GEMM: D[64,128] = M[64,128] x W[128,128]^T via mma.sync ----
        {
            const int rt = w & 3;        // row tile = batch in round
            const int ct = w >> 2;       // col tile (32 cols)
            float d[4][4];
#pragma unroll
            for (int nt = 0; nt < 4; nt++)
#pragma unroll
                for (int k = 0; k < 4; k++) d[nt][k] = 0.f;

            const uint32_t aBase = sb + OFF_M
                + (uint32_t)(rt * 16 + (lane & 15)) * WST + (uint32_t)((lane >> 4) * 16);
            const uint32_t bBase0 = sb + OFF_W
                + (uint32_t)(ct * 32 + (lane & 7) + ((lane >> 4) * 8)) * WST
                + (uint32_t)(((lane >> 3) & 1) * 16);
            const uint32_t bBase1 = bBase0 + 16 * WST;

#pragma unroll
            for (int s = 0; s < 8; s++) {
                uint32_t a[4], b0r[4], b1r[4];
                ldsm_x4(a,   aBase  + s * 32);
                ldsm_x4(b0r, bBase0 + s * 32);
                ldsm_x4(b1r, bBase1 + s * 32);
                mma16816(d[0], a, b0r + 0);
                mma16816(d[1], a, b0r + 2);
                mma16816(d[2], a, b1r + 0);
                mma16816(d[3], a, b1r + 2);
            }

            // ---- epilogue: bias + direct stores (guarded for partial rounds) ----
            if (rt < nb) {
                const int g = lane >> 2, t = lane & 3;
                float* ob = out + (size_t)(b0 + R * 4 + rt) * (NC * HID);
                float* o0 = ob + g * HID;
                float* o1 = ob + (g + 8) * HID;
#pragma unroll
                for (int nt = 0; nt < 4; nt++) {
                    int col = ct * 32 + nt * 8 + 2 * t;
                    float bv0 = s_bias[col], bv1 = s_bias[col + 1];
                    *(float2*)(o0 + col) = make_float2(d[nt][0] + bv0, d[nt][1] + bv1);
                    *(float2*)(o1 + col) = make_float2(d[nt][2] + bv0, d[nt][3] + bv1);
                }
            }
        }
        __syncthreads();
    }
}

extern "C" void kernel_launch(void* const* d_in, const int* in_sizes, int n_in,
                              void* d_out, int out_size) {
    const int*   la   = (const int*)  d_in[0];   // (2048, 512) int32
    const float* adj  = (const float*)d_in[1];   // (16, 16) f32
    const float* qemb = (const float*)d_in[2];   // (513, 128) f32
    const float* W    = (const float*)d_in[3];   // (128, 128) f32
    const float* bias = (const float*)d_in[4];   // (128,) f32
    float* out = (float*)d_out;                  // (2048, 16, 128) f32

    cudaFuncSetAttribute(enc_kernel, cudaFuncAttributeMaxDynamicSharedMemorySize, SMEM_REQ);
    prep_kernel<<<322, 256>>>(adj, W, qemb);
    enc_kernel<<<GRID, THREADS, SMEM_REQ>>>(la, bias, out);
}